// round 8
// baseline (speedup 1.0000x reference)
#include <cuda_runtime.h>
#include <cstdint>

#define Gg   100
#define G3   1000000
#define HW   327680      // (1280/2)*(1024/2) = 640*512
#define HMW2 640
#define Bsz  2
#define Csz  8
#define Jsz  12
#define VPT  4           // voxels per thread (along k; 100 % 4 == 0)
#define NTHREADS 256
#define NGROUPS  (G3 / VPT)   // 250000

__global__ __launch_bounds__(NTHREADS, 2) void reproj_kernel(
    const float* __restrict__ hm,      // [B,C,J,512,640]
    const float* __restrict__ center,  // [B,3]
    const float* __restrict__ Mg,      // [B,C,4,3]
    const float* __restrict__ intr,    // [B,C,3,3]
    const float* __restrict__ dist,    // [B,C,1,5]
    float* __restrict__ out)           // [B,J,100,100,100]
{
    __shared__ float sM[Csz][12];
    __shared__ float sPar[Csz][8];   // fx, fy, cx, cy, k1, k2, 1/fx, 1/fy

    const int b = blockIdx.y;
    const int t = threadIdx.x;

    if (t < Csz * 12) {
        sM[t / 12][t % 12] = Mg[b * Csz * 12 + t];
    } else if (t < Csz * 12 + Csz) {
        const int c = t - Csz * 12;
        const float* ic = intr + (b * Csz + c) * 9;
        const float fx = ic[0], fy = ic[4];
        sPar[c][0] = fx;
        sPar[c][1] = fy;
        sPar[c][2] = ic[6];   // cx
        sPar[c][3] = ic[7];   // cy
        const float* dc = dist + (b * Csz + c) * 5;
        sPar[c][4] = dc[0];   // k1
        sPar[c][5] = dc[1];   // k2
        sPar[c][6] = __frcp_rn(fx);
        sPar[c][7] = __frcp_rn(fy);
    }
    __syncthreads();

    const int m = blockIdx.x * NTHREADS + t;
    if (m >= NGROUPS) return;

    const int n_base = m * VPT;
    // n = i*10000 + jg*100 + kg ; groups of 4 never cross a jg row (100 % 4 == 0)
    const int i  = n_base / (Gg * Gg);
    const int r0 = n_base - i * (Gg * Gg);
    const int jg = r0 / Gg;
    const int kg = r0 - jg * Gg;

    const float cbx = center[b * 3 + 0];
    const float cby = center[b * 3 + 1];
    const float cbz = center[b * 3 + 2];

    const float x = __fadd_rn((float)(i  - 50) * 2.0f, cbx);
    const float y = __fadd_rn((float)(jg - 50) * 2.0f, cby);
    float zv[VPT];
#pragma unroll
    for (int v = 0; v < VPT; v++)
        zv[v] = __fadd_rn((float)(kg + v - 50) * 2.0f, cbz);

    float acc[Jsz][VPT];
#pragma unroll
    for (int j = 0; j < Jsz; j++)
#pragma unroll
        for (int v = 0; v < VPT; v++) acc[j][v] = 0.0f;

#pragma unroll
    for (int c = 0; c < Csz; c++) {
        const float* M = sM[c];
        const float fx = sPar[c][0], fy = sPar[c][1];
        const float cx = sPar[c][2], cy = sPar[c][3];
        const float k1 = sPar[c][4], k2 = sPar[c][5];
        const float rfx = sPar[c][6], rfy = sPar[c][7];

        // z-invariant partial sums: p = ((x*M0)+(y*M1)) + ((z*M2)+M3)
        // left pair is shared across the 4 voxels EXACTLY (same rounded ops)
        const float l0 = __fadd_rn(__fmul_rn(x, M[0]), __fmul_rn(y, M[3]));
        const float l1 = __fadd_rn(__fmul_rn(x, M[1]), __fmul_rn(y, M[4]));
        const float l2 = __fadd_rn(__fmul_rn(x, M[2]), __fmul_rn(y, M[5]));

        int idx[VPT];
#pragma unroll
        for (int v = 0; v < VPT; v++) {
            const float z = zv[v];
            const float p0 = __fadd_rn(l0, __fadd_rn(__fmul_rn(z, M[6]), M[9]));
            const float p1 = __fadd_rn(l1, __fadd_rn(__fmul_rn(z, M[7]), M[10]));
            const float p2 = __fadd_rn(l2, __fadd_rn(__fmul_rn(z, M[8]), M[11]));

            const float rp2 = __frcp_rn(p2);
            const float px  = __fmul_rn(p0, rp2);
            const float py  = __fmul_rn(p1, rp2);

            const float xn = __fmul_rn(__fsub_rn(px, cx), rfx);
            const float yn = __fmul_rn(__fsub_rn(py, cy), rfy);

            const float r2 = __fadd_rn(__fmul_rn(xn, xn), __fmul_rn(yn, yn));
            const float rad = __fadd_rn(__fadd_rn(1.0f, __fmul_rn(k1, r2)),
                                        __fmul_rn(__fmul_rn(k2, r2), r2));

            float xd = __fadd_rn(__fmul_rn(__fmul_rn(xn, rad), fx), cx);
            float yd = __fadd_rn(__fmul_rn(__fmul_rn(yn, rad), fy), cy);
            xd = fminf(fmaxf(xd, 0.0f), 1279.0f);
            yd = fminf(fmaxf(yd, 0.0f), 1023.0f);

            idx[v] = (int)(yd * 0.5f) * HMW2 + (int)(xd * 0.5f);
        }

        const float* hplane = hm + (size_t)(b * Csz + c) * Jsz * HW;

        const bool same = (idx[0] == idx[1]) & (idx[1] == idx[2]) & (idx[2] == idx[3]);
        if (__all_sync(0xffffffffu, same)) {
            // one gather serves all 4 voxels (values identical by construction)
            const float* hbase = hplane + idx[0];
#pragma unroll
            for (int j = 0; j < Jsz; j++) {
                const float val = __ldg(hbase + (size_t)j * HW);
                acc[j][0] = __fadd_rn(acc[j][0], val);
                acc[j][1] = __fadd_rn(acc[j][1], val);
                acc[j][2] = __fadd_rn(acc[j][2], val);
                acc[j][3] = __fadd_rn(acc[j][3], val);
            }
        } else {
#pragma unroll
            for (int j = 0; j < Jsz; j++) {
                const float* hj = hplane + (size_t)j * HW;
#pragma unroll
                for (int v = 0; v < VPT; v++)
                    acc[j][v] = __fadd_rn(acc[j][v], __ldg(hj + idx[v]));
            }
        }
    }

    float* ob = out + (size_t)b * Jsz * G3 + n_base;
#pragma unroll
    for (int j = 0; j < Jsz; j++) {
        float4 o;
        o.x = acc[j][0] * 0.125f;
        o.y = acc[j][1] * 0.125f;
        o.z = acc[j][2] * 0.125f;
        o.w = acc[j][3] * 0.125f;
        *(float4*)(ob + (size_t)j * G3) = o;
    }
}

extern "C" void kernel_launch(void* const* d_in, const int* in_sizes, int n_in,
                              void* d_out, int out_size)
{
    const float* hm     = (const float*)d_in[0];
    const float* center = (const float*)d_in[1];
    const float* Mg     = (const float*)d_in[2];
    const float* intr   = (const float*)d_in[3];
    const float* dist   = (const float*)d_in[4];
    float* out = (float*)d_out;

    dim3 grid((NGROUPS + NTHREADS - 1) / NTHREADS, Bsz);
    reproj_kernel<<<grid, NTHREADS>>>(hm, center, Mg, intr, dist, out);
}

// round 9
// speedup vs baseline: 1.0213x; 1.0213x over previous
#include <cuda_runtime.h>
#include <cstdint>

#define Gg   100
#define G3   1000000
#define HW   327680      // (1280/2)*(1024/2) = 640*512
#define HMW2 640
#define Bsz  2
#define Csz  8
#define Jsz  12
#define VPT  4           // voxels per thread (along k; 100 % 4 == 0)
#define NTHREADS 256
#define NGROUPS  (G3 / VPT)   // 250000

__global__ __launch_bounds__(NTHREADS, 2) void reproj_kernel(
    const float* __restrict__ hm,      // [B,C,J,512,640]
    const float* __restrict__ center,  // [B,3]
    const float* __restrict__ Mg,      // [B,C,4,3]
    const float* __restrict__ intr,    // [B,C,3,3]
    const float* __restrict__ dist,    // [B,C,1,5]
    float* __restrict__ out)           // [B,J,100,100,100]
{
    __shared__ float sM[Csz][12];
    __shared__ float sPar[Csz][8];   // fx, fy, cx, cy, k1, k2, 1/fx, 1/fy

    const int b = blockIdx.y;
    const int t = threadIdx.x;

    if (t < Csz * 12) {
        sM[t / 12][t % 12] = Mg[b * Csz * 12 + t];
    } else if (t < Csz * 12 + Csz) {
        const int c = t - Csz * 12;
        const float* ic = intr + (b * Csz + c) * 9;
        const float fx = ic[0], fy = ic[4];
        sPar[c][0] = fx;
        sPar[c][1] = fy;
        sPar[c][2] = ic[6];   // cx
        sPar[c][3] = ic[7];   // cy
        const float* dc = dist + (b * Csz + c) * 5;
        sPar[c][4] = dc[0];   // k1
        sPar[c][5] = dc[1];   // k2
        sPar[c][6] = __frcp_rn(fx);
        sPar[c][7] = __frcp_rn(fy);
    }
    __syncthreads();

    const int m = blockIdx.x * NTHREADS + t;
    if (m >= NGROUPS) return;

    const int n_base = m * VPT;
    // n = i*10000 + jg*100 + kg ; groups of 4 never cross a jg row (100 % 4 == 0)
    const int i  = n_base / (Gg * Gg);
    const int r0 = n_base - i * (Gg * Gg);
    const int jg = r0 / Gg;
    const int kg = r0 - jg * Gg;

    const float cbx = center[b * 3 + 0];
    const float cby = center[b * 3 + 1];
    const float cbz = center[b * 3 + 2];

    const float x = __fadd_rn((float)(i  - 50) * 2.0f, cbx);
    const float y = __fadd_rn((float)(jg - 50) * 2.0f, cby);
    float zv[VPT];
#pragma unroll
    for (int v = 0; v < VPT; v++)
        zv[v] = __fadd_rn((float)(kg + v - 50) * 2.0f, cbz);

    float acc[Jsz][VPT];
#pragma unroll
    for (int j = 0; j < Jsz; j++)
#pragma unroll
        for (int v = 0; v < VPT; v++) acc[j][v] = 0.0f;

#pragma unroll
    for (int c = 0; c < Csz; c++) {
        const float* M = sM[c];
        const float fx = sPar[c][0], fy = sPar[c][1];
        const float cx = sPar[c][2], cy = sPar[c][3];
        const float k1 = sPar[c][4], k2 = sPar[c][5];
        const float rfx = sPar[c][6], rfy = sPar[c][7];

        // z-invariant partial sums: p = ((x*M0)+(y*M1)) + ((z*M2)+M3)
        // left pair is shared across the 4 voxels EXACTLY (same rounded ops)
        const float l0 = __fadd_rn(__fmul_rn(x, M[0]), __fmul_rn(y, M[3]));
        const float l1 = __fadd_rn(__fmul_rn(x, M[1]), __fmul_rn(y, M[4]));
        const float l2 = __fadd_rn(__fmul_rn(x, M[2]), __fmul_rn(y, M[5]));

        int idx[VPT];
#pragma unroll
        for (int v = 0; v < VPT; v++) {
            const float z = zv[v];
            const float p0 = __fadd_rn(l0, __fadd_rn(__fmul_rn(z, M[6]), M[9]));
            const float p1 = __fadd_rn(l1, __fadd_rn(__fmul_rn(z, M[7]), M[10]));
            const float p2 = __fadd_rn(l2, __fadd_rn(__fmul_rn(z, M[8]), M[11]));

            const float rp2 = __frcp_rn(p2);
            const float px  = __fmul_rn(p0, rp2);
            const float py  = __fmul_rn(p1, rp2);

            const float xn = __fmul_rn(__fsub_rn(px, cx), rfx);
            const float yn = __fmul_rn(__fsub_rn(py, cy), rfy);

            const float r2 = __fadd_rn(__fmul_rn(xn, xn), __fmul_rn(yn, yn));
            const float rad = __fadd_rn(__fadd_rn(1.0f, __fmul_rn(k1, r2)),
                                        __fmul_rn(__fmul_rn(k2, r2), r2));

            float xd = __fadd_rn(__fmul_rn(__fmul_rn(xn, rad), fx), cx);
            float yd = __fadd_rn(__fmul_rn(__fmul_rn(yn, rad), fy), cy);
            xd = fminf(fmaxf(xd, 0.0f), 1279.0f);
            yd = fminf(fmaxf(yd, 0.0f), 1023.0f);

            idx[v] = (int)(yd * 0.5f) * HMW2 + (int)(xd * 0.5f);
        }

        const float* hplane = hm + (size_t)(b * Csz + c) * Jsz * HW;

        const bool same = (idx[0] == idx[1]) & (idx[1] == idx[2]) & (idx[2] == idx[3]);
        if (__all_sync(0xffffffffu, same)) {
            // one gather serves all 4 voxels (values identical by construction)
            const float* hbase = hplane + idx[0];
#pragma unroll
            for (int j = 0; j < Jsz; j++) {
                const float val = __ldg(hbase + (size_t)j * HW);
                acc[j][0] = __fadd_rn(acc[j][0], val);
                acc[j][1] = __fadd_rn(acc[j][1], val);
                acc[j][2] = __fadd_rn(acc[j][2], val);
                acc[j][3] = __fadd_rn(acc[j][3], val);
            }
        } else {
#pragma unroll
            for (int j = 0; j < Jsz; j++) {
                const float* hj = hplane + (size_t)j * HW;
#pragma unroll
                for (int v = 0; v < VPT; v++)
                    acc[j][v] = __fadd_rn(acc[j][v], __ldg(hj + idx[v]));
            }
        }
    }

    float* ob = out + (size_t)b * Jsz * G3 + n_base;
#pragma unroll
    for (int j = 0; j < Jsz; j++) {
        float4 o;
        o.x = acc[j][0] * 0.125f;
        o.y = acc[j][1] * 0.125f;
        o.z = acc[j][2] * 0.125f;
        o.w = acc[j][3] * 0.125f;
        *(float4*)(ob + (size_t)j * G3) = o;
    }
}

extern "C" void kernel_launch(void* const* d_in, const int* in_sizes, int n_in,
                              void* d_out, int out_size)
{
    const float* hm     = (const float*)d_in[0];
    const float* center = (const float*)d_in[1];
    const float* Mg     = (const float*)d_in[2];
    const float* intr   = (const float*)d_in[3];
    const float* dist   = (const float*)d_in[4];
    float* out = (float*)d_out;

    dim3 grid((NGROUPS + NTHREADS - 1) / NTHREADS, Bsz);
    reproj_kernel<<<grid, NTHREADS>>>(hm, center, Mg, intr, dist, out);
}